// round 16
// baseline (speedup 1.0000x reference)
#include <cuda_runtime.h>
#include <math.h>

#define N_NODES  100000
#define N_EDGES  1000000
#define N_GRAPHS 2048
#define F_IN     78
#define DIM      32
#define T_DIM    208
#define H1       170
#define H2       128
#define BN_EPS   1e-5f
#define DEG_CAP  64

// ---------------- scratch (device globals; no allocation allowed) ----------
__device__ float  d_proj[N_NODES * DIM];
__device__ float  d_hA[N_NODES * DIM];
__device__ float  d_hB[N_NODES * DIM];
__device__ double d_stat[3 * 2 * DIM];     // per layer: [sums(32), sumsq(32)]
__device__ float  d_t1[N_GRAPHS * H1];
__device__ float  d_t2[N_GRAPHS * H2];
__device__ float  d_tpart[2 * T_DIM];      // target col sums/sumsq (zero @load; tail re-zeros)
__device__ float  d_gpool[N_GRAPHS * DIM]; // pooled raw sums (zero @load; tail re-zeros)
__device__ int    d_deg[N_NODES];          // zero @load; tail re-zeros
__device__ int    d_adj[N_NODES * DEG_CAP];
__device__ int    d_goff[N_GRAPHS + 1];

#define PROJ_BLOCKS  1024
#define EDGE_BLOCKS  ((N_EDGES + 255) / 256)             // 3907
#define GOFF_BLOCKS  ((N_GRAPHS + 1 + 255) / 256)        // 9
#define TS_BLOCKS    32                                  // 64 rows each
#define T_BLOCKS     (N_GRAPHS / 16)                     // 128
#define MLP_BLOCKS   760                                 // +128 = 888 (one wave @6/SM)
#define TAIL_BLOCKS  (N_GRAPHS / 16)                     // 128

// ---------------- build: proj + adjacency + goff + coalesced target partials
__global__ void k_build(const int* __restrict__ src, const int* __restrict__ dst,
                        int* __restrict__ deg, int* __restrict__ adj,
                        const int* __restrict__ batch, int* __restrict__ goff,
                        const float* __restrict__ target,
                        float* __restrict__ tpart,
                        double* __restrict__ stat,
                        const float* __restrict__ x,
                        const float* __restrict__ Wp,
                        float* __restrict__ proj) {
    int b = blockIdx.x;
    if (b < PROJ_BLOCKS) {
        __shared__ float Ws[F_IN * DIM];
        for (int i = threadIdx.x; i < F_IN * DIM; i += blockDim.x) Ws[i] = Wp[i];
        __syncthreads();
        int lane = threadIdx.x & 31;
        int gwarp = (b * 256 + threadIdx.x) >> 5;
        const int nwarps = (PROJ_BLOCKS * 256) >> 5;
        for (int n = gwarp; n < N_NODES; n += nwarps) {
            const float* xr = x + (size_t)n * F_IN;
            float r0 = xr[lane];
            float r1 = xr[32 + lane];
            float r2 = (lane < F_IN - 64) ? xr[64 + lane] : 0.f;
            float acc = 0.f;
            #pragma unroll
            for (int k = 0; k < 32; k++)
                acc = fmaf(__shfl_sync(0xffffffffu, r0, k), Ws[k * DIM + lane], acc);
            #pragma unroll
            for (int k = 0; k < 32; k++)
                acc = fmaf(__shfl_sync(0xffffffffu, r1, k), Ws[(32 + k) * DIM + lane], acc);
            #pragma unroll
            for (int k = 0; k < F_IN - 64; k++)
                acc = fmaf(__shfl_sync(0xffffffffu, r2, k), Ws[(64 + k) * DIM + lane], acc);
            proj[n * DIM + lane] = acc;
        }
        return;
    }
    b -= PROJ_BLOCKS;
    if (b < EDGE_BLOCKS) {
        int i = b * 256 + threadIdx.x;
        if (i < N_EDGES) {
            int d = dst[i];
            int c = atomicAdd(&deg[d], 1);
            if (c < DEG_CAP) adj[d * DEG_CAP + c] = src[i];
        }
        return;
    }
    if (b < EDGE_BLOCKS + GOFF_BLOCKS) {
        int g = (b - EDGE_BLOCKS) * 256 + threadIdx.x;
        if (g > N_GRAPHS) return;
        int lo = 0, hi = N_NODES;
        while (lo < hi) { int mid = (lo + hi) >> 1; if (batch[mid] < g) lo = mid + 1; else hi = mid; }
        goff[g] = lo;
        return;
    }
    if (b < EDGE_BLOCKS + GOFF_BLOCKS + 1) {
        if (threadIdx.x < 3 * 2 * DIM) stat[threadIdx.x] = 0.0;
        return;
    }
    // target partial stats: 32 blocks x 64 rows, coalesced tile loads
    {
        int tb = b - (EDGE_BLOCKS + GOFF_BLOCKS + 1);
        const int row0 = tb * 64;
        __shared__ float tile[16][T_DIM + 1];
        float s = 0.f, q = 0.f;
        for (int t4 = 0; t4 < 4; t4++) {
            __syncthreads();
            for (int i = threadIdx.x; i < 16 * T_DIM; i += 256) {
                int r = i / T_DIM, c = i % T_DIM;
                tile[r][c] = target[(size_t)(row0 + t4 * 16 + r) * T_DIM + c];
            }
            __syncthreads();
            if (threadIdx.x < T_DIM) {
                #pragma unroll
                for (int r = 0; r < 16; r++) {
                    float v = tile[r][threadIdx.x];
                    s += v;
                    q = fmaf(v, v, q);
                }
            }
        }
        if (threadIdx.x < T_DIM) {
            atomicAdd(&tpart[threadIdx.x], s);
            atomicAdd(&tpart[T_DIM + threadIdx.x], q);
        }
    }
}

// Target-branch blocks, W-streaming form (TP: 1=t1 GEMM, 2=t2 GEMM+softmax).
template <int TP>
__device__ __forceinline__ void target_branch(int tb,
                          const float* __restrict__ tin,
                          const float* __restrict__ tpart,   // TP1: partial stats
                          const float* __restrict__ tg1,     // TP1
                          const float* __restrict__ tbe1,    // TP1
                          const float* __restrict__ Wt,
                          const float* __restrict__ bt,
                          float* __restrict__ tout) {
    if (TP == 1) {
        __shared__ float ABs[2][T_DIM];
        __shared__ float tn[16][T_DIM];
        const int row0 = tb * 16;
        for (int t = threadIdx.x; t < T_DIM; t += 256) {
            float m = tpart[t] * (1.f / N_GRAPHS);
            float v = tpart[T_DIM + t] * (1.f / N_GRAPHS) - m * m;
            float inv = rsqrtf(v + BN_EPS);
            float A = tg1[t] * inv;
            ABs[0][t] = A;
            ABs[1][t] = tbe1[t] - m * A;
        }
        __syncthreads();
        for (int i = threadIdx.x; i < 16 * T_DIM; i += 256) {
            int r = i / T_DIM, c = i % T_DIM;
            tn[r][c] = fmaf(tin[(row0 + r) * T_DIM + c], ABs[0][c], ABs[1][c]);
        }
        __syncthreads();
        int j = threadIdx.x;
        if (j < H1) {
            float bj = bt[j];
            #pragma unroll
            for (int half = 0; half < 2; half++) {
                float acc[8];
                #pragma unroll
                for (int r = 0; r < 8; r++) acc[r] = bj;
                for (int c = 0; c < T_DIM; c++) {
                    float w = Wt[c * H1 + j];
                    #pragma unroll
                    for (int r = 0; r < 8; r++)
                        acc[r] = fmaf(tn[half * 8 + r][c], w, acc[r]);
                }
                #pragma unroll
                for (int r = 0; r < 8; r++)
                    tout[(row0 + half * 8 + r) * H1 + j] = acc[r];
            }
        }
    } else {
        __shared__ float t1s[16][H1 + 2];
        __shared__ float so[16][H2];
        const int row0 = tb * 16;
        for (int i = threadIdx.x; i < 16 * H1; i += 256) {
            int r = i / H1, c = i % H1;
            t1s[r][c] = tin[(row0 + r) * H1 + c];
        }
        __syncthreads();
        int j = threadIdx.x;
        if (j < H2) {
            float bj = bt[j];
            #pragma unroll
            for (int half = 0; half < 2; half++) {
                float acc[8];
                #pragma unroll
                for (int r = 0; r < 8; r++) acc[r] = bj;
                for (int c = 0; c < H1; c++) {
                    float w = Wt[c * H2 + j];
                    #pragma unroll
                    for (int r = 0; r < 8; r++)
                        acc[r] = fmaf(t1s[half * 8 + r][c], w, acc[r]);
                }
                #pragma unroll
                for (int r = 0; r < 8; r++)
                    so[half * 8 + r][j] = acc[r];
            }
        }
        __syncthreads();
        int wid = threadIdx.x >> 5, lane = threadIdx.x & 31;
        #pragma unroll
        for (int rr = 0; rr < 2; rr++) {
            int r = wid * 2 + rr;
            float v0 = so[r][lane],      v1 = so[r][32 + lane];
            float v2 = so[r][64 + lane], v3 = so[r][96 + lane];
            float m = fmaxf(fmaxf(v0, v1), fmaxf(v2, v3));
            #pragma unroll
            for (int o = 16; o > 0; o >>= 1)
                m = fmaxf(m, __shfl_xor_sync(0xffffffffu, m, o));
            float e0 = expf(v0 - m), e1 = expf(v1 - m);
            float e2 = expf(v2 - m), e3 = expf(v3 - m);
            float s = (e0 + e1) + (e2 + e3);
            #pragma unroll
            for (int o = 16; o > 0; o >>= 1)
                s += __shfl_xor_sync(0xffffffffu, s, o);
            float inv = 1.f / s;
            tout[(row0 + r) * H2 + lane]      = e0 * inv;
            tout[(row0 + r) * H2 + 32 + lane] = e1 * inv;
            tout[(row0 + r) * H2 + 64 + lane] = e2 * inv;
            tout[(row0 + r) * H2 + 96 + lane] = e3 * inv;
        }
    }
}

// Fused GIN layer, 4 nodes per warp / float4 per lane (8 lanes per node).
// POOL=1 (layer 3): additionally reduce o into gpool[batch[n]] via float atomics.
template <int NMAT, int TP, int POOL>
__global__ void __launch_bounds__(256, 6)
k_agg(const float* __restrict__ hin,
      const int* __restrict__ deg,
      const int* __restrict__ adj,
      const double* __restrict__ statp,
      const float* __restrict__ W1,
      const float* __restrict__ b1,
      const float* __restrict__ W2,
      const float* __restrict__ b2,
      float* __restrict__ hout,
      double* __restrict__ stat,
      const float* __restrict__ tin,
      const float* __restrict__ tpart,
      const float* __restrict__ tg1,
      const float* __restrict__ tbe1,
      const float* __restrict__ Wt,
      const float* __restrict__ bt,
      float* __restrict__ tout,
      const int* __restrict__ batch,
      float* __restrict__ gpool) {
    if (TP != 0 && blockIdx.x < T_BLOCKS) {
        target_branch<TP>(blockIdx.x, tin, tpart, tg1, tbe1, Wt, bt, tout);
        return;
    }
    const int abid    = (TP != 0) ? (blockIdx.x - T_BLOCKS) : blockIdx.x;
    const int nblocks = (TP != 0) ? (gridDim.x - T_BLOCKS) : gridDim.x;

    __shared__ float4 W1q[DIM][8];
    __shared__ float4 W2q[DIM][8];
    __shared__ float4 baddq[8], b1q[8], b2q[8];
    __shared__ float  red[2 * DIM];

    float* W1f   = (float*)W1q;
    float* W2f   = (float*)W2q;
    float* badds = (float*)baddq;
    float* b1s   = (float*)b1q;
    float* b2s   = (float*)b2q;
    const int tid = threadIdx.x;

    if (tid < 32) {
        int j = tid;
        if (NMAT == 2) {
            double m = statp[j] * (1.0 / N_NODES);
            double v = statp[DIM + j] * (1.0 / N_NODES) - m * m;
            float sc = (float)(1.0 / sqrt(v + (double)BN_EPS));
            float sh = (float)(-m) * sc;
            float bacc = 0.f;
            #pragma unroll
            for (int k = 0; k < DIM; k++) {
                float w = W1[k * DIM + j];
                W1f[k * DIM + j] = __shfl_sync(0xffffffffu, sc, k) * w;
                bacc = fmaf(__shfl_sync(0xffffffffu, sh, k), w, bacc);
            }
            badds[j] = bacc;
        }
        b1s[j] = b1[j];
        b2s[j] = b2[j];
    }
    for (int i = tid; i < DIM * DIM; i += 256) W2f[i] = W2[i];
    if (tid < 2 * DIM) red[tid] = 0.f;
    __syncthreads();

    const int lane = tid & 31;
    const int g    = lane >> 3;
    const int sl   = lane & 7;
    const int gb   = g << 3;
    const int gwarp = (abid * 256 + tid) >> 5;
    const int stride4 = (nblocks * 8) * 4;
    float4 lsum = make_float4(0.f, 0.f, 0.f, 0.f);
    float4 lsq  = make_float4(0.f, 0.f, 0.f, 0.f);

    for (int n4 = gwarp * 4; n4 < N_NODES; n4 += stride4) {
        const int n = n4 + g;
        const int dT = deg[n];
        int dn = dT > DEG_CAP ? DEG_CAP : dT;
        const int* an = adj + (size_t)n * DEG_CAP;

        float4 z = *(const float4*)(hin + (size_t)n * DIM + sl * 4);

        for (int base = 0; base < dn; base += 8) {
            int4 i0 = *(const int4*)(an + base);
            int4 i1 = *(const int4*)(an + base + 4);
            int rem = dn - base;
            if (rem >= 8) {
                float4 t0 = *(const float4*)(hin + (size_t)i0.x * DIM + sl * 4);
                float4 t1 = *(const float4*)(hin + (size_t)i0.y * DIM + sl * 4);
                float4 t2 = *(const float4*)(hin + (size_t)i0.z * DIM + sl * 4);
                float4 t3 = *(const float4*)(hin + (size_t)i0.w * DIM + sl * 4);
                float4 t4 = *(const float4*)(hin + (size_t)i1.x * DIM + sl * 4);
                float4 t5 = *(const float4*)(hin + (size_t)i1.y * DIM + sl * 4);
                float4 t6 = *(const float4*)(hin + (size_t)i1.z * DIM + sl * 4);
                float4 t7 = *(const float4*)(hin + (size_t)i1.w * DIM + sl * 4);
                z.x += ((t0.x + t1.x) + (t2.x + t3.x)) + ((t4.x + t5.x) + (t6.x + t7.x));
                z.y += ((t0.y + t1.y) + (t2.y + t3.y)) + ((t4.y + t5.y) + (t6.y + t7.y));
                z.z += ((t0.z + t1.z) + (t2.z + t3.z)) + ((t4.z + t5.z) + (t6.z + t7.z));
                z.w += ((t0.w + t1.w) + (t2.w + t3.w)) + ((t4.w + t5.w) + (t6.w + t7.w));
            } else {
                #pragma unroll
                for (int k = 0; k < 7; k++) {
                    if (k < rem) {
                        int s = (k < 4) ? ((const int*)&i0)[k] : ((const int*)&i1)[k - 4];
                        float4 t = *(const float4*)(hin + (size_t)s * DIM + sl * 4);
                        z.x += t.x; z.y += t.y; z.z += t.z; z.w += t.w;
                    }
                }
            }
        }

        if (NMAT == 1) {
            float4 bb1 = b1q[sl];
            z.x = fmaxf(z.x + bb1.x, 0.f);
            z.y = fmaxf(z.y + bb1.y, 0.f);
            z.z = fmaxf(z.z + bb1.z, 0.f);
            z.w = fmaxf(z.w + bb1.w, 0.f);
        } else {
            float df = (float)(1 + dT);
            float4 bd  = baddq[sl];
            float4 bb1 = b1q[sl];
            float4 a;
            a.x = fmaf(df, bd.x, bb1.x);
            a.y = fmaf(df, bd.y, bb1.y);
            a.z = fmaf(df, bd.z, bb1.z);
            a.w = fmaf(df, bd.w, bb1.w);
            #pragma unroll
            for (int kq = 0; kq < 8; kq++) {
                float zx = __shfl_sync(0xffffffffu, z.x, gb + kq);
                float zy = __shfl_sync(0xffffffffu, z.y, gb + kq);
                float zz = __shfl_sync(0xffffffffu, z.z, gb + kq);
                float zw = __shfl_sync(0xffffffffu, z.w, gb + kq);
                float4 w;
                w = W1q[4 * kq + 0][sl];
                a.x = fmaf(zx, w.x, a.x); a.y = fmaf(zx, w.y, a.y);
                a.z = fmaf(zx, w.z, a.z); a.w = fmaf(zx, w.w, a.w);
                w = W1q[4 * kq + 1][sl];
                a.x = fmaf(zy, w.x, a.x); a.y = fmaf(zy, w.y, a.y);
                a.z = fmaf(zy, w.z, a.z); a.w = fmaf(zy, w.w, a.w);
                w = W1q[4 * kq + 2][sl];
                a.x = fmaf(zz, w.x, a.x); a.y = fmaf(zz, w.y, a.y);
                a.z = fmaf(zz, w.z, a.z); a.w = fmaf(zz, w.w, a.w);
                w = W1q[4 * kq + 3][sl];
                a.x = fmaf(zw, w.x, a.x); a.y = fmaf(zw, w.y, a.y);
                a.z = fmaf(zw, w.z, a.z); a.w = fmaf(zw, w.w, a.w);
            }
            z.x = fmaxf(a.x, 0.f);
            z.y = fmaxf(a.y, 0.f);
            z.z = fmaxf(a.z, 0.f);
            z.w = fmaxf(a.w, 0.f);
        }

        float4 o = b2q[sl];
        #pragma unroll
        for (int kq = 0; kq < 8; kq++) {
            float zx = __shfl_sync(0xffffffffu, z.x, gb + kq);
            float zy = __shfl_sync(0xffffffffu, z.y, gb + kq);
            float zz = __shfl_sync(0xffffffffu, z.z, gb + kq);
            float zw = __shfl_sync(0xffffffffu, z.w, gb + kq);
            float4 w;
            w = W2q[4 * kq + 0][sl];
            o.x = fmaf(zx, w.x, o.x); o.y = fmaf(zx, w.y, o.y);
            o.z = fmaf(zx, w.z, o.z); o.w = fmaf(zx, w.w, o.w);
            w = W2q[4 * kq + 1][sl];
            o.x = fmaf(zy, w.x, o.x); o.y = fmaf(zy, w.y, o.y);
            o.z = fmaf(zy, w.z, o.z); o.w = fmaf(zy, w.w, o.w);
            w = W2q[4 * kq + 2][sl];
            o.x = fmaf(zz, w.x, o.x); o.y = fmaf(zz, w.y, o.y);
            o.z = fmaf(zz, w.z, o.z); o.w = fmaf(zz, w.w, o.w);
            w = W2q[4 * kq + 3][sl];
            o.x = fmaf(zw, w.x, o.x); o.y = fmaf(zw, w.y, o.y);
            o.z = fmaf(zw, w.z, o.z); o.w = fmaf(zw, w.w, o.w);
        }
        if (NMAT == 1) {
            o.x = (o.x > 0.f) ? o.x : expm1f(o.x);
            o.y = (o.y > 0.f) ? o.y : expm1f(o.y);
            o.z = (o.z > 0.f) ? o.z : expm1f(o.z);
            o.w = (o.w > 0.f) ? o.w : expm1f(o.w);
        } else {
            o.x = fmaxf(o.x, 0.f);
            o.y = fmaxf(o.y, 0.f);
            o.z = fmaxf(o.z, 0.f);
            o.w = fmaxf(o.w, 0.f);
        }
        *(float4*)(hout + (size_t)n * DIM + sl * 4) = o;
        if (POOL) {
            float* gp = gpool + (size_t)batch[n] * DIM + sl * 4;
            atomicAdd(gp + 0, o.x);
            atomicAdd(gp + 1, o.y);
            atomicAdd(gp + 2, o.z);
            atomicAdd(gp + 3, o.w);
        }
        lsum.x += o.x; lsq.x = fmaf(o.x, o.x, lsq.x);
        lsum.y += o.y; lsq.y = fmaf(o.y, o.y, lsq.y);
        lsum.z += o.z; lsq.z = fmaf(o.z, o.z, lsq.z);
        lsum.w += o.w; lsq.w = fmaf(o.w, o.w, lsq.w);
    }

    atomicAdd(&red[4 * sl + 0], lsum.x);
    atomicAdd(&red[4 * sl + 1], lsum.y);
    atomicAdd(&red[4 * sl + 2], lsum.z);
    atomicAdd(&red[4 * sl + 3], lsum.w);
    atomicAdd(&red[DIM + 4 * sl + 0], lsq.x);
    atomicAdd(&red[DIM + 4 * sl + 1], lsq.y);
    atomicAdd(&red[DIM + 4 * sl + 2], lsq.z);
    atomicAdd(&red[DIM + 4 * sl + 3], lsq.w);
    __syncthreads();
    if (tid < 2 * DIM)
        atomicAdd(&stat[tid], (double)red[tid]);
}

// Fused graph tail, W-streaming: 16 graphs per block. Reads gpool (no h re-read).
// Also re-zeros deg, tpart, and the gpool rows it consumed.
__global__ void __launch_bounds__(256)
k_tail(const float* __restrict__ gpool_c,
       float* __restrict__ gpool,
       const double* __restrict__ statp,
       const int* __restrict__ goff,
       const float* __restrict__ Wn2, const float* __restrict__ bn2b,
       const float* __restrict__ t2,
       const float* __restrict__ W4, const float* __restrict__ b4,
       const float* __restrict__ W5, const float* __restrict__ b5,
       float* __restrict__ outg,
       float* __restrict__ out,
       int* __restrict__ deg,
       float* __restrict__ tpart) {
    __shared__ float ss_s[2 * DIM];
    __shared__ float gs[16][DIM];
    __shared__ float xc[16][256];
    __shared__ float part[16][128];
    __shared__ float yv[16][128];
    const int tid = threadIdx.x;
    const int b0 = blockIdx.x * 16;
    for (int i = blockIdx.x * 256 + tid; i < N_NODES; i += TAIL_BLOCKS * 256)
        deg[i] = 0;
    if (blockIdx.x == 0 && tid < 2 * T_DIM) tpart[tid] = 0.f;
    if (tid < 32) {
        double m = statp[tid] * (1.0 / N_NODES);
        double v = statp[DIM + tid] * (1.0 / N_NODES) - m * m;
        float sc = (float)(1.0 / sqrt(v + (double)BN_EPS));
        ss_s[tid]       = sc;
        ss_s[DIM + tid] = (float)(-m) * sc;
    }
    __syncthreads();
    // pooled BN: 512 items = 16 graphs x 32 feats; read gpool then zero it
    #pragma unroll
    for (int p = 0; p < 2; p++) {
        int idx = p * 256 + tid;
        int gi = idx >> 5, f = idx & 31;
        int gr = b0 + gi;
        float val = gpool_c[(size_t)gr * DIM + f];
        int cnt = goff[gr + 1] - goff[gr];
        gs[gi][f] = fmaf(ss_s[f], val, ss_s[DIM + f] * (float)cnt);
        gpool[(size_t)gr * DIM + f] = 0.f;   // re-zero for next replay
    }
    __syncthreads();
    // g2 = relu(gs @ Wn2 + bn2b): threads 0-127 compute; 128-255 stage t2
    if (tid < 128) {
        float acc[16];
        float bj = bn2b[tid];
        #pragma unroll
        for (int r = 0; r < 16; r++) acc[r] = bj;
        for (int k = 0; k < DIM; k++) {
            float w = Wn2[k * H2 + tid];
            #pragma unroll
            for (int r = 0; r < 16; r++) acc[r] = fmaf(gs[r][k], w, acc[r]);
        }
        #pragma unroll
        for (int r = 0; r < 16; r++) {
            float v = fmaxf(acc[r], 0.f);
            outg[(b0 + r) * H2 + tid] = v;
            xc[r][tid] = v;
        }
    } else {
        int j = tid - 128;
        #pragma unroll
        for (int r = 0; r < 16; r++)
            xc[r][128 + j] = t2[(b0 + r) * H2 + j];
    }
    __syncthreads();
    {
        int j = tid & 127;
        int half = tid >> 7;
        float acc[16];
        #pragma unroll
        for (int r = 0; r < 16; r++) acc[r] = 0.f;
        int k0 = half * 128;
        for (int k = k0; k < k0 + 128; k++) {
            float w = W4[k * H2 + j];
            #pragma unroll
            for (int r = 0; r < 16; r++) acc[r] = fmaf(xc[r][k], w, acc[r]);
        }
        if (half == 1) {
            #pragma unroll
            for (int r = 0; r < 16; r++) part[r][j] = acc[r];
        }
        __syncthreads();
        if (half == 0) {
            float bj = b4[j];
            float w5 = W5[j];
            #pragma unroll
            for (int r = 0; r < 16; r++) {
                float y = fmaxf(acc[r] + part[r][j] + bj, 0.f);
                yv[r][j] = y * w5;
            }
        }
    }
    __syncthreads();
    const int wid = tid >> 5, lane = tid & 31;
    #pragma unroll
    for (int gg = 0; gg < 2; gg++) {
        int r = wid * 2 + gg;
        float v = (yv[r][lane] + yv[r][32 + lane]) + (yv[r][64 + lane] + yv[r][96 + lane]);
        #pragma unroll
        for (int o = 16; o > 0; o >>= 1) v += __shfl_xor_sync(0xffffffffu, v, o);
        if (lane == 0) out[b0 + r] = 1.f / (1.f + expf(-(v + b5[0])));
    }
}

// ---------------- launch ----------------------------------------------------

extern "C" void kernel_launch(void* const* d_in, const int* in_sizes, int n_in,
                              void* d_out, int out_size) {
    const float* x       = (const float*)d_in[0];
    const int*   ei      = (const int*)d_in[1];
    const int*   batch   = (const int*)d_in[2];
    const float* target  = (const float*)d_in[3];
    const float* W11a = (const float*)d_in[4];   const float* b11a = (const float*)d_in[5];
    const float* W11b = (const float*)d_in[6];   const float* b11b = (const float*)d_in[7];
    const float* W12a = (const float*)d_in[8];   const float* b12a = (const float*)d_in[9];
    const float* W12b = (const float*)d_in[10];  const float* b12b = (const float*)d_in[11];
    const float* W13a = (const float*)d_in[12];  const float* b13a = (const float*)d_in[13];
    const float* W13b = (const float*)d_in[14];  const float* b13b = (const float*)d_in[15];
    const float* Wn2  = (const float*)d_in[16];  const float* bn2b = (const float*)d_in[17];
    const float* g1   = (const float*)d_in[18];  const float* be1  = (const float*)d_in[19];
    const float* W31  = (const float*)d_in[20];  const float* b31  = (const float*)d_in[21];
    const float* W32  = (const float*)d_in[22];  const float* b32  = (const float*)d_in[23];
    const float* W4   = (const float*)d_in[24];  const float* b4   = (const float*)d_in[25];
    const float* W5   = (const float*)d_in[26];  const float* b5   = (const float*)d_in[27];
    (void)in_sizes; (void)n_in; (void)out_size;

    const int* src = ei;
    const int* dst = ei + N_EDGES;

    float* out  = (float*)d_out;          // [0, 2048): sigmoid out
    float* outg = out + N_GRAPHS;         // [2048, ...): g2 [2048,128]

    void *pProj, *pHA, *pHB, *pStat, *pT1, *pT2, *pTP, *pGP, *pDeg, *pAdj, *pGoff;
    cudaGetSymbolAddress(&pProj, d_proj);
    cudaGetSymbolAddress(&pHA,   d_hA);
    cudaGetSymbolAddress(&pHB,   d_hB);
    cudaGetSymbolAddress(&pStat, d_stat);
    cudaGetSymbolAddress(&pT1,   d_t1);
    cudaGetSymbolAddress(&pT2,   d_t2);
    cudaGetSymbolAddress(&pTP,   d_tpart);
    cudaGetSymbolAddress(&pGP,   d_gpool);
    cudaGetSymbolAddress(&pDeg,  d_deg);
    cudaGetSymbolAddress(&pAdj,  d_adj);
    cudaGetSymbolAddress(&pGoff, d_goff);

    float*  proj = (float*)pProj;
    float*  hA   = (float*)pHA;
    float*  hB   = (float*)pHB;
    double* stat = (double*)pStat;
    float*  t1b  = (float*)pT1;
    float*  t2b  = (float*)pT2;
    float*  tpart= (float*)pTP;
    float*  gpool= (float*)pGP;
    int*    deg  = (int*)pDeg;
    int*    adj  = (int*)pAdj;
    int*    goff = (int*)pGoff;

    const int BUILD_BLOCKS = PROJ_BLOCKS + EDGE_BLOCKS + GOFF_BLOCKS + 1 + TS_BLOCKS;

    // 1: proj + adjacency + goff + target partial stats + zero layer-stats
    k_build<<<BUILD_BLOCKS, 256>>>(src, dst, deg, adj, batch, goff, target,
                                   tpart, stat, x, W11a, proj);

    // 2: layer 1 (elu) + piggyback t1 (front of grid)
    k_agg<1, 1, 0><<<MLP_BLOCKS + T_BLOCKS, 256>>>(proj, deg, adj, (const double*)0,
                                                   (const float*)0, b11a, W11b, b11b,
                                                   hA, stat, target, tpart, g1, be1,
                                                   W31, b31, t1b, (const int*)0, (float*)0);

    // 3: layer 2 + piggyback t2 (front of grid)
    k_agg<2, 2, 0><<<MLP_BLOCKS + T_BLOCKS, 256>>>(hA, deg, adj, stat,
                                                   W12a, b12a, W12b, b12b,
                                                   hB, stat + 2 * DIM, t1b, (const float*)0,
                                                   (const float*)0, (const float*)0,
                                                   W32, b32, t2b, (const int*)0, (float*)0);

    // 4: layer 3 + fused pooling (full 888-block wave)
    k_agg<2, 0, 1><<<MLP_BLOCKS + T_BLOCKS, 256>>>(hB, deg, adj, stat + 2 * DIM,
                                                   W13a, b13a, W13b, b13b,
                                                   hA, stat + 4 * DIM, (const float*)0,
                                                   (const float*)0, (const float*)0,
                                                   (const float*)0, (const float*)0,
                                                   (const float*)0, (float*)0, batch, gpool);

    // 5: fused graph tail (reads gpool; re-zeros deg/tpart/gpool)
    k_tail<<<TAIL_BLOCKS, 256>>>(gpool, gpool, stat + 4 * DIM, goff, Wn2, bn2b, t2b,
                                 W4, b4, W5, b5, outg, out, deg, tpart);
}

// round 17
// speedup vs baseline: 1.0088x; 1.0088x over previous
#include <cuda_runtime.h>
#include <math.h>

#define N_NODES  100000
#define N_EDGES  1000000
#define N_GRAPHS 2048
#define F_IN     78
#define DIM      32
#define T_DIM    208
#define H1       170
#define H2       128
#define BN_EPS   1e-5f
#define DEG_CAP  64

// ---------------- scratch (device globals; no allocation allowed) ----------
__device__ float  d_proj[N_NODES * DIM];
__device__ float  d_hA[N_NODES * DIM];
__device__ float  d_hB[N_NODES * DIM];
__device__ double d_stat[3 * 2 * DIM];     // per layer: [sums(32), sumsq(32)]
__device__ float  d_t1[N_GRAPHS * H1];
__device__ float  d_t2[N_GRAPHS * H2];
__device__ float  d_tpart[2 * T_DIM];      // target col sums/sumsq (zero @load; tail re-zeros)
__device__ int    d_deg[N_NODES];          // zero @load; tail re-zeros
__device__ int    d_adj[N_NODES * DEG_CAP];
__device__ int    d_goff[N_GRAPHS + 1];

#define PROJ_BLOCKS  1024
#define EDGE_BLOCKS  ((N_EDGES + 255) / 256)             // 3907
#define GOFF_BLOCKS  ((N_GRAPHS + 1 + 255) / 256)        // 9
#define TS_BLOCKS    32                                  // 64 rows each
#define T_BLOCKS     (N_GRAPHS / 16)                     // 128
#define MLP_BLOCKS   760                                 // +128 = 888 (one wave @6/SM)
#define TAIL_BLOCKS  (N_GRAPHS / 16)                     // 128

// ---------------- build: proj + adjacency + goff + coalesced target partials
__global__ void k_build(const int* __restrict__ src, const int* __restrict__ dst,
                        int* __restrict__ deg, int* __restrict__ adj,
                        const int* __restrict__ batch, int* __restrict__ goff,
                        const float* __restrict__ target,
                        float* __restrict__ tpart,
                        double* __restrict__ stat,
                        const float* __restrict__ x,
                        const float* __restrict__ Wp,
                        float* __restrict__ proj) {
    int b = blockIdx.x;
    if (b < PROJ_BLOCKS) {
        __shared__ float Ws[F_IN * DIM];
        for (int i = threadIdx.x; i < F_IN * DIM; i += blockDim.x) Ws[i] = Wp[i];
        __syncthreads();
        int lane = threadIdx.x & 31;
        int gwarp = (b * 256 + threadIdx.x) >> 5;
        const int nwarps = (PROJ_BLOCKS * 256) >> 5;
        for (int n = gwarp; n < N_NODES; n += nwarps) {
            const float* xr = x + (size_t)n * F_IN;
            float r0 = xr[lane];
            float r1 = xr[32 + lane];
            float r2 = (lane < F_IN - 64) ? xr[64 + lane] : 0.f;
            float acc = 0.f;
            #pragma unroll
            for (int k = 0; k < 32; k++)
                acc = fmaf(__shfl_sync(0xffffffffu, r0, k), Ws[k * DIM + lane], acc);
            #pragma unroll
            for (int k = 0; k < 32; k++)
                acc = fmaf(__shfl_sync(0xffffffffu, r1, k), Ws[(32 + k) * DIM + lane], acc);
            #pragma unroll
            for (int k = 0; k < F_IN - 64; k++)
                acc = fmaf(__shfl_sync(0xffffffffu, r2, k), Ws[(64 + k) * DIM + lane], acc);
            proj[n * DIM + lane] = acc;
        }
        return;
    }
    b -= PROJ_BLOCKS;
    if (b < EDGE_BLOCKS) {
        int i = b * 256 + threadIdx.x;
        if (i < N_EDGES) {
            int d = dst[i];
            int c = atomicAdd(&deg[d], 1);
            if (c < DEG_CAP) adj[d * DEG_CAP + c] = src[i];
        }
        return;
    }
    if (b < EDGE_BLOCKS + GOFF_BLOCKS) {
        int g = (b - EDGE_BLOCKS) * 256 + threadIdx.x;
        if (g > N_GRAPHS) return;
        int lo = 0, hi = N_NODES;
        while (lo < hi) { int mid = (lo + hi) >> 1; if (batch[mid] < g) lo = mid + 1; else hi = mid; }
        goff[g] = lo;
        return;
    }
    if (b < EDGE_BLOCKS + GOFF_BLOCKS + 1) {
        if (threadIdx.x < 3 * 2 * DIM) stat[threadIdx.x] = 0.0;
        return;
    }
    // target partial stats: 32 blocks x 64 rows, coalesced tile loads
    {
        int tb = b - (EDGE_BLOCKS + GOFF_BLOCKS + 1);
        const int row0 = tb * 64;
        __shared__ float tile[16][T_DIM + 1];
        float s = 0.f, q = 0.f;
        for (int t4 = 0; t4 < 4; t4++) {
            __syncthreads();
            for (int i = threadIdx.x; i < 16 * T_DIM; i += 256) {
                int r = i / T_DIM, c = i % T_DIM;
                tile[r][c] = target[(size_t)(row0 + t4 * 16 + r) * T_DIM + c];
            }
            __syncthreads();
            if (threadIdx.x < T_DIM) {
                #pragma unroll
                for (int r = 0; r < 16; r++) {
                    float v = tile[r][threadIdx.x];
                    s += v;
                    q = fmaf(v, v, q);
                }
            }
        }
        if (threadIdx.x < T_DIM) {
            atomicAdd(&tpart[threadIdx.x], s);
            atomicAdd(&tpart[T_DIM + threadIdx.x], q);
        }
    }
}

// Target-branch blocks, W-streaming form (TP: 1=t1 GEMM, 2=t2 GEMM+softmax).
template <int TP>
__device__ __forceinline__ void target_branch(int tb,
                          const float* __restrict__ tin,
                          const float* __restrict__ tpart,   // TP1: partial stats
                          const float* __restrict__ tg1,     // TP1
                          const float* __restrict__ tbe1,    // TP1
                          const float* __restrict__ Wt,
                          const float* __restrict__ bt,
                          float* __restrict__ tout) {
    if (TP == 1) {
        __shared__ float ABs[2][T_DIM];
        __shared__ float tn[16][T_DIM];
        const int row0 = tb * 16;
        for (int t = threadIdx.x; t < T_DIM; t += 256) {
            float m = tpart[t] * (1.f / N_GRAPHS);
            float v = tpart[T_DIM + t] * (1.f / N_GRAPHS) - m * m;
            float inv = rsqrtf(v + BN_EPS);
            float A = tg1[t] * inv;
            ABs[0][t] = A;
            ABs[1][t] = tbe1[t] - m * A;
        }
        __syncthreads();
        for (int i = threadIdx.x; i < 16 * T_DIM; i += 256) {
            int r = i / T_DIM, c = i % T_DIM;
            tn[r][c] = fmaf(tin[(row0 + r) * T_DIM + c], ABs[0][c], ABs[1][c]);
        }
        __syncthreads();
        int j = threadIdx.x;
        if (j < H1) {
            float bj = bt[j];
            #pragma unroll
            for (int half = 0; half < 2; half++) {
                float acc[8];
                #pragma unroll
                for (int r = 0; r < 8; r++) acc[r] = bj;
                for (int c = 0; c < T_DIM; c++) {
                    float w = Wt[c * H1 + j];
                    #pragma unroll
                    for (int r = 0; r < 8; r++)
                        acc[r] = fmaf(tn[half * 8 + r][c], w, acc[r]);
                }
                #pragma unroll
                for (int r = 0; r < 8; r++)
                    tout[(row0 + half * 8 + r) * H1 + j] = acc[r];
            }
        }
    } else {
        __shared__ float t1s[16][H1 + 2];
        __shared__ float so[16][H2];
        const int row0 = tb * 16;
        for (int i = threadIdx.x; i < 16 * H1; i += 256) {
            int r = i / H1, c = i % H1;
            t1s[r][c] = tin[(row0 + r) * H1 + c];
        }
        __syncthreads();
        int j = threadIdx.x;
        if (j < H2) {
            float bj = bt[j];
            #pragma unroll
            for (int half = 0; half < 2; half++) {
                float acc[8];
                #pragma unroll
                for (int r = 0; r < 8; r++) acc[r] = bj;
                for (int c = 0; c < H1; c++) {
                    float w = Wt[c * H2 + j];
                    #pragma unroll
                    for (int r = 0; r < 8; r++)
                        acc[r] = fmaf(t1s[half * 8 + r][c], w, acc[r]);
                }
                #pragma unroll
                for (int r = 0; r < 8; r++)
                    so[half * 8 + r][j] = acc[r];
            }
        }
        __syncthreads();
        int wid = threadIdx.x >> 5, lane = threadIdx.x & 31;
        #pragma unroll
        for (int rr = 0; rr < 2; rr++) {
            int r = wid * 2 + rr;
            float v0 = so[r][lane],      v1 = so[r][32 + lane];
            float v2 = so[r][64 + lane], v3 = so[r][96 + lane];
            float m = fmaxf(fmaxf(v0, v1), fmaxf(v2, v3));
            #pragma unroll
            for (int o = 16; o > 0; o >>= 1)
                m = fmaxf(m, __shfl_xor_sync(0xffffffffu, m, o));
            float e0 = expf(v0 - m), e1 = expf(v1 - m);
            float e2 = expf(v2 - m), e3 = expf(v3 - m);
            float s = (e0 + e1) + (e2 + e3);
            #pragma unroll
            for (int o = 16; o > 0; o >>= 1)
                s += __shfl_xor_sync(0xffffffffu, s, o);
            float inv = 1.f / s;
            tout[(row0 + r) * H2 + lane]      = e0 * inv;
            tout[(row0 + r) * H2 + 32 + lane] = e1 * inv;
            tout[(row0 + r) * H2 + 64 + lane] = e2 * inv;
            tout[(row0 + r) * H2 + 96 + lane] = e3 * inv;
        }
    }
}

// Fused GIN layer, 4 nodes per warp / float4 per lane (8 lanes per node).
template <int NMAT, int TP>
__global__ void __launch_bounds__(256, 6)
k_agg(const float* __restrict__ hin,
      const int* __restrict__ deg,
      const int* __restrict__ adj,
      const double* __restrict__ statp,
      const float* __restrict__ W1,
      const float* __restrict__ b1,
      const float* __restrict__ W2,
      const float* __restrict__ b2,
      float* __restrict__ hout,
      double* __restrict__ stat,
      const float* __restrict__ tin,
      const float* __restrict__ tpart,
      const float* __restrict__ tg1,
      const float* __restrict__ tbe1,
      const float* __restrict__ Wt,
      const float* __restrict__ bt,
      float* __restrict__ tout) {
    if (TP != 0 && blockIdx.x < T_BLOCKS) {
        target_branch<TP>(blockIdx.x, tin, tpart, tg1, tbe1, Wt, bt, tout);
        return;
    }
    const int abid    = (TP != 0) ? (blockIdx.x - T_BLOCKS) : blockIdx.x;
    const int nblocks = (TP != 0) ? (gridDim.x - T_BLOCKS) : gridDim.x;

    __shared__ float4 W1q[DIM][8];
    __shared__ float4 W2q[DIM][8];
    __shared__ float4 baddq[8], b1q[8], b2q[8];
    __shared__ float  red[2 * DIM];

    float* W1f   = (float*)W1q;
    float* W2f   = (float*)W2q;
    float* badds = (float*)baddq;
    float* b1s   = (float*)b1q;
    float* b2s   = (float*)b2q;
    const int tid = threadIdx.x;

    if (tid < 32) {
        int j = tid;
        if (NMAT == 2) {
            double m = statp[j] * (1.0 / N_NODES);
            double v = statp[DIM + j] * (1.0 / N_NODES) - m * m;
            float sc = (float)(1.0 / sqrt(v + (double)BN_EPS));
            float sh = (float)(-m) * sc;
            float bacc = 0.f;
            #pragma unroll
            for (int k = 0; k < DIM; k++) {
                float w = W1[k * DIM + j];
                W1f[k * DIM + j] = __shfl_sync(0xffffffffu, sc, k) * w;
                bacc = fmaf(__shfl_sync(0xffffffffu, sh, k), w, bacc);
            }
            badds[j] = bacc;
        }
        b1s[j] = b1[j];
        b2s[j] = b2[j];
    }
    for (int i = tid; i < DIM * DIM; i += 256) W2f[i] = W2[i];
    if (tid < 2 * DIM) red[tid] = 0.f;
    __syncthreads();

    const int lane = tid & 31;
    const int g    = lane >> 3;
    const int sl   = lane & 7;
    const int gb   = g << 3;
    const int gwarp = (abid * 256 + tid) >> 5;
    const int stride4 = (nblocks * 8) * 4;
    float4 lsum = make_float4(0.f, 0.f, 0.f, 0.f);
    float4 lsq  = make_float4(0.f, 0.f, 0.f, 0.f);

    for (int n4 = gwarp * 4; n4 < N_NODES; n4 += stride4) {
        const int n = n4 + g;
        const int dT = deg[n];
        int dn = dT > DEG_CAP ? DEG_CAP : dT;
        const int* an = adj + (size_t)n * DEG_CAP;

        float4 z = *(const float4*)(hin + (size_t)n * DIM + sl * 4);

        for (int base = 0; base < dn; base += 8) {
            int4 i0 = *(const int4*)(an + base);
            int4 i1 = *(const int4*)(an + base + 4);
            int rem = dn - base;
            if (rem >= 8) {
                float4 t0 = *(const float4*)(hin + (size_t)i0.x * DIM + sl * 4);
                float4 t1 = *(const float4*)(hin + (size_t)i0.y * DIM + sl * 4);
                float4 t2 = *(const float4*)(hin + (size_t)i0.z * DIM + sl * 4);
                float4 t3 = *(const float4*)(hin + (size_t)i0.w * DIM + sl * 4);
                float4 t4 = *(const float4*)(hin + (size_t)i1.x * DIM + sl * 4);
                float4 t5 = *(const float4*)(hin + (size_t)i1.y * DIM + sl * 4);
                float4 t6 = *(const float4*)(hin + (size_t)i1.z * DIM + sl * 4);
                float4 t7 = *(const float4*)(hin + (size_t)i1.w * DIM + sl * 4);
                z.x += ((t0.x + t1.x) + (t2.x + t3.x)) + ((t4.x + t5.x) + (t6.x + t7.x));
                z.y += ((t0.y + t1.y) + (t2.y + t3.y)) + ((t4.y + t5.y) + (t6.y + t7.y));
                z.z += ((t0.z + t1.z) + (t2.z + t3.z)) + ((t4.z + t5.z) + (t6.z + t7.z));
                z.w += ((t0.w + t1.w) + (t2.w + t3.w)) + ((t4.w + t5.w) + (t6.w + t7.w));
            } else {
                #pragma unroll
                for (int k = 0; k < 7; k++) {
                    if (k < rem) {
                        int s = (k < 4) ? ((const int*)&i0)[k] : ((const int*)&i1)[k - 4];
                        float4 t = *(const float4*)(hin + (size_t)s * DIM + sl * 4);
                        z.x += t.x; z.y += t.y; z.z += t.z; z.w += t.w;
                    }
                }
            }
        }

        if (NMAT == 1) {
            float4 bb1 = b1q[sl];
            z.x = fmaxf(z.x + bb1.x, 0.f);
            z.y = fmaxf(z.y + bb1.y, 0.f);
            z.z = fmaxf(z.z + bb1.z, 0.f);
            z.w = fmaxf(z.w + bb1.w, 0.f);
        } else {
            float df = (float)(1 + dT);
            float4 bd  = baddq[sl];
            float4 bb1 = b1q[sl];
            float4 a;
            a.x = fmaf(df, bd.x, bb1.x);
            a.y = fmaf(df, bd.y, bb1.y);
            a.z = fmaf(df, bd.z, bb1.z);
            a.w = fmaf(df, bd.w, bb1.w);
            #pragma unroll
            for (int kq = 0; kq < 8; kq++) {
                float zx = __shfl_sync(0xffffffffu, z.x, gb + kq);
                float zy = __shfl_sync(0xffffffffu, z.y, gb + kq);
                float zz = __shfl_sync(0xffffffffu, z.z, gb + kq);
                float zw = __shfl_sync(0xffffffffu, z.w, gb + kq);
                float4 w;
                w = W1q[4 * kq + 0][sl];
                a.x = fmaf(zx, w.x, a.x); a.y = fmaf(zx, w.y, a.y);
                a.z = fmaf(zx, w.z, a.z); a.w = fmaf(zx, w.w, a.w);
                w = W1q[4 * kq + 1][sl];
                a.x = fmaf(zy, w.x, a.x); a.y = fmaf(zy, w.y, a.y);
                a.z = fmaf(zy, w.z, a.z); a.w = fmaf(zy, w.w, a.w);
                w = W1q[4 * kq + 2][sl];
                a.x = fmaf(zz, w.x, a.x); a.y = fmaf(zz, w.y, a.y);
                a.z = fmaf(zz, w.z, a.z); a.w = fmaf(zz, w.w, a.w);
                w = W1q[4 * kq + 3][sl];
                a.x = fmaf(zw, w.x, a.x); a.y = fmaf(zw, w.y, a.y);
                a.z = fmaf(zw, w.z, a.z); a.w = fmaf(zw, w.w, a.w);
            }
            z.x = fmaxf(a.x, 0.f);
            z.y = fmaxf(a.y, 0.f);
            z.z = fmaxf(a.z, 0.f);
            z.w = fmaxf(a.w, 0.f);
        }

        float4 o = b2q[sl];
        #pragma unroll
        for (int kq = 0; kq < 8; kq++) {
            float zx = __shfl_sync(0xffffffffu, z.x, gb + kq);
            float zy = __shfl_sync(0xffffffffu, z.y, gb + kq);
            float zz = __shfl_sync(0xffffffffu, z.z, gb + kq);
            float zw = __shfl_sync(0xffffffffu, z.w, gb + kq);
            float4 w;
            w = W2q[4 * kq + 0][sl];
            o.x = fmaf(zx, w.x, o.x); o.y = fmaf(zx, w.y, o.y);
            o.z = fmaf(zx, w.z, o.z); o.w = fmaf(zx, w.w, o.w);
            w = W2q[4 * kq + 1][sl];
            o.x = fmaf(zy, w.x, o.x); o.y = fmaf(zy, w.y, o.y);
            o.z = fmaf(zy, w.z, o.z); o.w = fmaf(zy, w.w, o.w);
            w = W2q[4 * kq + 2][sl];
            o.x = fmaf(zz, w.x, o.x); o.y = fmaf(zz, w.y, o.y);
            o.z = fmaf(zz, w.z, o.z); o.w = fmaf(zz, w.w, o.w);
            w = W2q[4 * kq + 3][sl];
            o.x = fmaf(zw, w.x, o.x); o.y = fmaf(zw, w.y, o.y);
            o.z = fmaf(zw, w.z, o.z); o.w = fmaf(zw, w.w, o.w);
        }
        if (NMAT == 1) {
            o.x = (o.x > 0.f) ? o.x : expm1f(o.x);
            o.y = (o.y > 0.f) ? o.y : expm1f(o.y);
            o.z = (o.z > 0.f) ? o.z : expm1f(o.z);
            o.w = (o.w > 0.f) ? o.w : expm1f(o.w);
        } else {
            o.x = fmaxf(o.x, 0.f);
            o.y = fmaxf(o.y, 0.f);
            o.z = fmaxf(o.z, 0.f);
            o.w = fmaxf(o.w, 0.f);
        }
        *(float4*)(hout + (size_t)n * DIM + sl * 4) = o;
        lsum.x += o.x; lsq.x = fmaf(o.x, o.x, lsq.x);
        lsum.y += o.y; lsq.y = fmaf(o.y, o.y, lsq.y);
        lsum.z += o.z; lsq.z = fmaf(o.z, o.z, lsq.z);
        lsum.w += o.w; lsq.w = fmaf(o.w, o.w, lsq.w);
    }

    atomicAdd(&red[4 * sl + 0], lsum.x);
    atomicAdd(&red[4 * sl + 1], lsum.y);
    atomicAdd(&red[4 * sl + 2], lsum.z);
    atomicAdd(&red[4 * sl + 3], lsum.w);
    atomicAdd(&red[DIM + 4 * sl + 0], lsq.x);
    atomicAdd(&red[DIM + 4 * sl + 1], lsq.y);
    atomicAdd(&red[DIM + 4 * sl + 2], lsq.z);
    atomicAdd(&red[DIM + 4 * sl + 3], lsq.w);
    __syncthreads();
    if (tid < 2 * DIM)
        atomicAdd(&stat[tid], (double)red[tid]);
}

// Fused graph tail, W-streaming: 16 graphs per block; pools from h directly.
// Also re-zeros deg and tpart.
__global__ void __launch_bounds__(256)
k_tail(const float* __restrict__ h,
       const double* __restrict__ statp,
       const int* __restrict__ goff,
       const float* __restrict__ Wn2, const float* __restrict__ bn2b,
       const float* __restrict__ t2,
       const float* __restrict__ W4, const float* __restrict__ b4,
       const float* __restrict__ W5, const float* __restrict__ b5,
       float* __restrict__ outg,
       float* __restrict__ out,
       int* __restrict__ deg,
       float* __restrict__ tpart) {
    __shared__ float ss_s[2 * DIM];
    __shared__ float gs[16][DIM];
    __shared__ float xc[16][256];
    __shared__ float part[16][128];
    __shared__ float yv[16][128];
    const int tid = threadIdx.x;
    const int b0 = blockIdx.x * 16;
    for (int i = blockIdx.x * 256 + tid; i < N_NODES; i += TAIL_BLOCKS * 256)
        deg[i] = 0;
    if (blockIdx.x == 0 && tid < 2 * T_DIM) tpart[tid] = 0.f;
    if (tid < 32) {
        double m = statp[tid] * (1.0 / N_NODES);
        double v = statp[DIM + tid] * (1.0 / N_NODES) - m * m;
        float sc = (float)(1.0 / sqrt(v + (double)BN_EPS));
        ss_s[tid]       = sc;
        ss_s[DIM + tid] = (float)(-m) * sc;
    }
    __syncthreads();
    const int wid = tid >> 5, lane = tid & 31;
    // pool: 8 warps x 2 graphs each
    #pragma unroll
    for (int gg = 0; gg < 2; gg++) {
        int gi = wid * 2 + gg;
        int gr = b0 + gi;
        int s0 = goff[gr], s1 = goff[gr + 1];
        float acc = 0.f;
        for (int n = s0; n < s1; n++) acc += h[n * DIM + lane];
        gs[gi][lane] = fmaf(ss_s[lane], acc, ss_s[DIM + lane] * (float)(s1 - s0));
    }
    __syncthreads();
    // g2 = relu(gs @ Wn2 + bn2b): threads 0-127 compute; 128-255 stage t2
    if (tid < 128) {
        float acc[16];
        float bj = bn2b[tid];
        #pragma unroll
        for (int r = 0; r < 16; r++) acc[r] = bj;
        for (int k = 0; k < DIM; k++) {
            float w = Wn2[k * H2 + tid];
            #pragma unroll
            for (int r = 0; r < 16; r++) acc[r] = fmaf(gs[r][k], w, acc[r]);
        }
        #pragma unroll
        for (int r = 0; r < 16; r++) {
            float v = fmaxf(acc[r], 0.f);
            outg[(b0 + r) * H2 + tid] = v;
            xc[r][tid] = v;
        }
    } else {
        int j = tid - 128;
        #pragma unroll
        for (int r = 0; r < 16; r++)
            xc[r][128 + j] = t2[(b0 + r) * H2 + j];
    }
    __syncthreads();
    {
        int j = tid & 127;
        int half = tid >> 7;
        float acc[16];
        #pragma unroll
        for (int r = 0; r < 16; r++) acc[r] = 0.f;
        int k0 = half * 128;
        for (int k = k0; k < k0 + 128; k++) {
            float w = W4[k * H2 + j];
            #pragma unroll
            for (int r = 0; r < 16; r++) acc[r] = fmaf(xc[r][k], w, acc[r]);
        }
        if (half == 1) {
            #pragma unroll
            for (int r = 0; r < 16; r++) part[r][j] = acc[r];
        }
        __syncthreads();
        if (half == 0) {
            float bj = b4[j];
            float w5 = W5[j];
            #pragma unroll
            for (int r = 0; r < 16; r++) {
                float y = fmaxf(acc[r] + part[r][j] + bj, 0.f);
                yv[r][j] = y * w5;
            }
        }
    }
    __syncthreads();
    #pragma unroll
    for (int gg = 0; gg < 2; gg++) {
        int r = wid * 2 + gg;
        float v = (yv[r][lane] + yv[r][32 + lane]) + (yv[r][64 + lane] + yv[r][96 + lane]);
        #pragma unroll
        for (int o = 16; o > 0; o >>= 1) v += __shfl_xor_sync(0xffffffffu, v, o);
        if (lane == 0) out[b0 + r] = 1.f / (1.f + expf(-(v + b5[0])));
    }
}

// ---------------- launch ----------------------------------------------------

extern "C" void kernel_launch(void* const* d_in, const int* in_sizes, int n_in,
                              void* d_out, int out_size) {
    const float* x       = (const float*)d_in[0];
    const int*   ei      = (const int*)d_in[1];
    const int*   batch   = (const int*)d_in[2];
    const float* target  = (const float*)d_in[3];
    const float* W11a = (const float*)d_in[4];   const float* b11a = (const float*)d_in[5];
    const float* W11b = (const float*)d_in[6];   const float* b11b = (const float*)d_in[7];
    const float* W12a = (const float*)d_in[8];   const float* b12a = (const float*)d_in[9];
    const float* W12b = (const float*)d_in[10];  const float* b12b = (const float*)d_in[11];
    const float* W13a = (const float*)d_in[12];  const float* b13a = (const float*)d_in[13];
    const float* W13b = (const float*)d_in[14];  const float* b13b = (const float*)d_in[15];
    const float* Wn2  = (const float*)d_in[16];  const float* bn2b = (const float*)d_in[17];
    const float* g1   = (const float*)d_in[18];  const float* be1  = (const float*)d_in[19];
    const float* W31  = (const float*)d_in[20];  const float* b31  = (const float*)d_in[21];
    const float* W32  = (const float*)d_in[22];  const float* b32  = (const float*)d_in[23];
    const float* W4   = (const float*)d_in[24];  const float* b4   = (const float*)d_in[25];
    const float* W5   = (const float*)d_in[26];  const float* b5   = (const float*)d_in[27];
    (void)in_sizes; (void)n_in; (void)out_size;

    const int* src = ei;
    const int* dst = ei + N_EDGES;

    float* out  = (float*)d_out;          // [0, 2048): sigmoid out
    float* outg = out + N_GRAPHS;         // [2048, ...): g2 [2048,128]

    void *pProj, *pHA, *pHB, *pStat, *pT1, *pT2, *pTP, *pDeg, *pAdj, *pGoff;
    cudaGetSymbolAddress(&pProj, d_proj);
    cudaGetSymbolAddress(&pHA,   d_hA);
    cudaGetSymbolAddress(&pHB,   d_hB);
    cudaGetSymbolAddress(&pStat, d_stat);
    cudaGetSymbolAddress(&pT1,   d_t1);
    cudaGetSymbolAddress(&pT2,   d_t2);
    cudaGetSymbolAddress(&pTP,   d_tpart);
    cudaGetSymbolAddress(&pDeg,  d_deg);
    cudaGetSymbolAddress(&pAdj,  d_adj);
    cudaGetSymbolAddress(&pGoff, d_goff);

    float*  proj = (float*)pProj;
    float*  hA   = (float*)pHA;
    float*  hB   = (float*)pHB;
    double* stat = (double*)pStat;
    float*  t1b  = (float*)pT1;
    float*  t2b  = (float*)pT2;
    float*  tpart= (float*)pTP;
    int*    deg  = (int*)pDeg;
    int*    adj  = (int*)pAdj;
    int*    goff = (int*)pGoff;

    const int BUILD_BLOCKS = PROJ_BLOCKS + EDGE_BLOCKS + GOFF_BLOCKS + 1 + TS_BLOCKS;

    // 1: proj + adjacency + goff + target partial stats + zero layer-stats
    k_build<<<BUILD_BLOCKS, 256>>>(src, dst, deg, adj, batch, goff, target,
                                   tpart, stat, x, W11a, proj);

    // 2: layer 1 (elu) + piggyback t1 (front of grid)
    k_agg<1, 1><<<MLP_BLOCKS + T_BLOCKS, 256>>>(proj, deg, adj, (const double*)0,
                                                (const float*)0, b11a, W11b, b11b,
                                                hA, stat, target, tpart, g1, be1,
                                                W31, b31, t1b);

    // 3: layer 2 + piggyback t2 (front of grid)
    k_agg<2, 2><<<MLP_BLOCKS + T_BLOCKS, 256>>>(hA, deg, adj, stat,
                                                W12a, b12a, W12b, b12b,
                                                hB, stat + 2 * DIM, t1b, (const float*)0,
                                                (const float*)0, (const float*)0,
                                                W32, b32, t2b);

    // 4: layer 3 (full 888-block wave)
    k_agg<2, 0><<<MLP_BLOCKS + T_BLOCKS, 256>>>(hB, deg, adj, stat + 2 * DIM,
                                                W13a, b13a, W13b, b13b,
                                                hA, stat + 4 * DIM, (const float*)0,
                                                (const float*)0, (const float*)0,
                                                (const float*)0, (const float*)0,
                                                (const float*)0, (float*)0);

    // 5: fused graph tail (pools h; re-zeros deg/tpart)
    k_tail<<<TAIL_BLOCKS, 256>>>(hA, stat + 4 * DIM, goff, Wn2, bn2b, t2b,
                                 W4, b4, W5, b5, outg, out, deg, tpart);
}